// round 13
// baseline (speedup 1.0000x reference)
#include <cuda_runtime.h>
#include <cuda_fp16.h>

#define NN 50000
#define EE 800000
#define DD 128
#define BN_EPS 1e-5f
#define B_FRONT 296
#define BNF_BLOCKS 296

// ---- scratch (device globals: zero-initialized at module load) ----
__device__ __align__(16) unsigned g_xwh32[NN * 64];  // x@W as half2 pairs
__device__ float    g_agg[NN * DD];
__device__ float    g_dinv[NN];
__device__ int      g_degi[NN];               // re-zeroed by k_gather each run
__device__ int      g_off[NN + 1];
__device__ int      g_cur[NN];
__device__ int      g_adj[EE];
__device__ int      g_bsum[256];              // chunk totals (<=196 used)
__device__ float    g_colsum[DD];             // zeroed in k_front each run
__device__ float    g_colsumsq[DD];
__device__ int      g_bar, g_done;            // front barrier counters
__device__ int      g_c3, g_c4;               // bnfinal barrier counters

// ---- per-block edge dtype self-detection (first 256 entries as int64) ----
__device__ __forceinline__ int detect_is64(const void* ei, int N, int tid) {
    __shared__ int s_is64;
    long long v = ((const long long*)ei)[tid & 255];
    int bad = (v < 0 || v >= N) ? 1 : 0;
    int any = __syncthreads_or(bad);
    if (tid == 0) s_is64 = !any;
    __syncthreads();
    return s_is64;
}

// ---- grid barrier (co-resident blocks; cumulative target) ----
__device__ __forceinline__ void gridbar(int phase) {
    __syncthreads();
    if (threadIdx.x == 0) {
        __threadfence();
        atomicAdd(&g_bar, 1);
        int target = phase * gridDim.x;
        while (atomicAdd(&g_bar, 0) < target) { }
    }
    __syncthreads();
}

// ---- K1: fused CSR build: prep -> scan -> offsets -> fill ----
__global__ __launch_bounds__(256) void k_front(const void* __restrict__ ei, int E, int N) {
    __shared__ int warp_tot[8];
    __shared__ int s_boff;
    int tid = threadIdx.x;
    int bid = blockIdx.x;
    int lane = tid & 31, wid = tid >> 5;
    int is64 = detect_is64(ei, N, tid);
    int gstride = gridDim.x * 256;

    // ---- phase P: degree histogram ----
    for (int e = bid * 256 + tid; e < E; e += gstride) {
        int row = is64 ? (int)((const long long*)ei)[e] : ((const int*)ei)[e];
        if ((unsigned)row < (unsigned)N) atomicAdd(&g_degi[row], 1);
    }
    gridbar(1);

    // ---- phase S1: local scan of 256-node chunk ----
    int nchunk = (N + 255) >> 8;
    int i = bid * 256 + tid;
    int v = 0, incl = 0;
    if (bid < nchunk) {
        v = (i < N) ? g_degi[i] : 0;
        int s = v;
#pragma unroll
        for (int d = 1; d < 32; d <<= 1) {
            int t = __shfl_up_sync(0xffffffffu, s, d);
            if (lane >= d) s += t;
        }
        if (lane == 31) warp_tot[wid] = s;
        __syncthreads();
        if (tid == 0) {
            int run = 0;
#pragma unroll
            for (int w = 0; w < 8; w++) { int t = warp_tot[w]; warp_tot[w] = run; run += t; }
        }
        __syncthreads();
        incl = s + warp_tot[wid];
        if (tid == 255) g_bsum[bid] = incl;
    }
    gridbar(2);

    // ---- phase S2: chunk prefix + write offsets/cursors/dinv ----
    if (bid < nchunk) {
        if (wid == 0) {
            int acc = 0;
            for (int b = lane; b < bid; b += 32) acc += g_bsum[b];
#pragma unroll
            for (int d = 16; d >= 1; d >>= 1) acc += __shfl_down_sync(0xffffffffu, acc, d);
            if (lane == 0) s_boff = acc;
        }
        __syncthreads();
        int fin = incl + s_boff;
        if (i < N) {
            g_off[i + 1] = fin;
            g_cur[i] = fin - v;
            g_dinv[i] = rsqrtf((float)(v + 1));
        }
    }
    if (bid == 0 && tid == 0) g_off[0] = 0;
    if (bid == 1 && tid < DD) { g_colsum[tid] = 0.f; g_colsumsq[tid] = 0.f; }
    gridbar(3);

    // ---- phase F: CSR fill ----
    for (int e = bid * 256 + tid; e < E; e += gstride) {
        int row, col;
        if (is64) {
            row = (int)((const long long*)ei)[e];
            col = (int)((const long long*)ei)[E + e];
        } else {
            row = ((const int*)ei)[e];
            col = ((const int*)ei)[E + e];
        }
        if ((unsigned)row >= (unsigned)N || (unsigned)col >= (unsigned)N) continue;
        int pos = atomicAdd(&g_cur[row], 1);
        g_adj[pos] = col;
    }

    // reset barrier counters for next replay (last block through)
    __syncthreads();
    if (tid == 0) {
        if (atomicAdd(&g_done, 1) == gridDim.x - 1) { g_bar = 0; g_done = 0; }
    }
}

// ---- K2: xw = x @ W via TF32 mma.sync (warp = 16 rows; W cvt inline) ----
__global__ __launch_bounds__(256) void k_gemm_tc(const float* __restrict__ x,
                                                 const float* __restrict__ W, int N) {
    int lane = threadIdx.x & 31;
    int warp = (blockIdx.x * blockDim.x + threadIdx.x) >> 5;
    int r0 = warp * 16;
    if (r0 >= N) return;
    int gid = lane >> 2;
    int tig = lane & 3;

    float c[16][4];
#pragma unroll
    for (int nt = 0; nt < 16; nt++)
        c[nt][0] = c[nt][1] = c[nt][2] = c[nt][3] = 0.f;

    const float* xr0 = x + (r0 + gid) * DD;
    const float* xr1 = xr0 + 8 * DD;

#pragma unroll
    for (int kt = 0; kt < 16; kt++) {
        int k0 = kt * 8;
        unsigned A0, A1, A2, A3;
        {
            float a0 = xr0[k0 + tig];
            float a1 = xr1[k0 + tig];
            float a2 = xr0[k0 + tig + 4];
            float a3 = xr1[k0 + tig + 4];
            asm("cvt.rna.tf32.f32 %0, %1;" : "=r"(A0) : "f"(a0));
            asm("cvt.rna.tf32.f32 %0, %1;" : "=r"(A1) : "f"(a1));
            asm("cvt.rna.tf32.f32 %0, %1;" : "=r"(A2) : "f"(a2));
            asm("cvt.rna.tf32.f32 %0, %1;" : "=r"(A3) : "f"(a3));
        }
#pragma unroll
        for (int nt = 0; nt < 16; nt++) {
            float b0f = W[(k0 + tig) * DD + nt * 8 + gid];
            float b1f = W[(k0 + tig + 4) * DD + nt * 8 + gid];
            unsigned B0, B1;
            asm("cvt.rna.tf32.f32 %0, %1;" : "=r"(B0) : "f"(b0f));
            asm("cvt.rna.tf32.f32 %0, %1;" : "=r"(B1) : "f"(b1f));
            asm volatile(
                "mma.sync.aligned.m16n8k8.row.col.f32.tf32.tf32.f32 "
                "{%0,%1,%2,%3}, {%4,%5,%6,%7}, {%8,%9}, {%0,%1,%2,%3};"
                : "+f"(c[nt][0]), "+f"(c[nt][1]), "+f"(c[nt][2]), "+f"(c[nt][3])
                : "r"(A0), "r"(A1), "r"(A2), "r"(A3), "r"(B0), "r"(B1));
        }
    }

    int row0 = r0 + gid, row1 = r0 + 8 + gid;
#pragma unroll
    for (int nt = 0; nt < 16; nt++) {
        int cH = (nt * 8 + 2 * tig) >> 1;
        __half2 h0 = __float22half2_rn(make_float2(c[nt][0], c[nt][1]));
        __half2 h1 = __float22half2_rn(make_float2(c[nt][2], c[nt][3]));
        g_xwh32[row0 * 64 + cH] = *(unsigned*)&h0;
        g_xwh32[row1 * 64 + cH] = *(unsigned*)&h1;
    }
}

// ---- K3: per-node gather (unroll-4) + re-zero degi for next run ----
__global__ __launch_bounds__(256) void k_gather(int N) {
    int gt = blockIdx.x * blockDim.x + threadIdx.x;
    if (gt < N) g_degi[gt] = 0;
    int lane = threadIdx.x & 31;
    int n = gt >> 5;
    if (n >= N) return;
    int j = g_off[n], end = g_off[n + 1];
    const uint2* xwh = (const uint2*)g_xwh32;

    float4 acc = make_float4(0.f, 0.f, 0.f, 0.f);
    for (; j + 4 <= end; j += 4) {
        int c0 = g_adj[j], c1 = g_adj[j + 1], c2 = g_adj[j + 2], c3 = g_adj[j + 3];
        float w0 = g_dinv[c0], w1 = g_dinv[c1], w2 = g_dinv[c2], w3 = g_dinv[c3];
        uint2 u0 = xwh[c0 * 32 + lane];
        uint2 u1 = xwh[c1 * 32 + lane];
        uint2 u2 = xwh[c2 * 32 + lane];
        uint2 u3 = xwh[c3 * 32 + lane];
        float2 a0 = __half22float2(*(__half2*)&u0.x), b0 = __half22float2(*(__half2*)&u0.y);
        float2 a1 = __half22float2(*(__half2*)&u1.x), b1 = __half22float2(*(__half2*)&u1.y);
        float2 a2 = __half22float2(*(__half2*)&u2.x), b2 = __half22float2(*(__half2*)&u2.y);
        float2 a3 = __half22float2(*(__half2*)&u3.x), b3 = __half22float2(*(__half2*)&u3.y);
        acc.x = fmaf(a0.x, w0, fmaf(a1.x, w1, fmaf(a2.x, w2, fmaf(a3.x, w3, acc.x))));
        acc.y = fmaf(a0.y, w0, fmaf(a1.y, w1, fmaf(a2.y, w2, fmaf(a3.y, w3, acc.y))));
        acc.z = fmaf(b0.x, w0, fmaf(b1.x, w1, fmaf(b2.x, w2, fmaf(b3.x, w3, acc.z))));
        acc.w = fmaf(b0.y, w0, fmaf(b1.y, w1, fmaf(b2.y, w2, fmaf(b3.y, w3, acc.w))));
    }
    for (; j < end; j++) {
        int c0 = g_adj[j];
        float w0 = g_dinv[c0];
        uint2 u0 = xwh[c0 * 32 + lane];
        float2 a0 = __half22float2(*(__half2*)&u0.x), b0 = __half22float2(*(__half2*)&u0.y);
        acc.x = fmaf(a0.x, w0, acc.x);
        acc.y = fmaf(a0.y, w0, acc.y);
        acc.z = fmaf(b0.x, w0, acc.z);
        acc.w = fmaf(b0.y, w0, acc.w);
    }
    float dr = g_dinv[n];
    uint2 us = xwh[n * 32 + lane];
    float2 sa = __half22float2(*(__half2*)&us.x), sb = __half22float2(*(__half2*)&us.y);
    acc.x = (acc.x + sa.x * dr) * dr;
    acc.y = (acc.y + sa.y * dr) * dr;
    acc.z = (acc.z + sb.x * dr) * dr;
    acc.w = (acc.w + sb.y * dr) * dr;
    ((float4*)g_agg)[n * 32 + lane] = acc;
}

// ---- K4: BN stats + finalize fused (persistent, spin grid barrier) ----
__global__ __launch_bounds__(256) void k_bnfinal(const float* __restrict__ x,
                                                 const float* __restrict__ gamma,
                                                 const float* __restrict__ beta,
                                                 float* __restrict__ out,
                                                 int N, float nInv) {
    __shared__ float s_a[DD], s_b[DD];
    int tid = threadIdx.x;
    int c = tid & 127, half = tid >> 7;

    float s = 0.f, s2 = 0.f;
    for (int r = blockIdx.x * 2 + half; r < N; r += gridDim.x * 2) {
        float v = g_agg[r * DD + c];
        s += v;
        s2 = fmaf(v, v, s2);
    }
    if (half == 0) { s_a[c] = s; s_b[c] = s2; }
    __syncthreads();
    if (half == 1) { s_a[c] += s; s_b[c] += s2; }
    __syncthreads();
    if (tid < DD) {
        atomicAdd(&g_colsum[tid], s_a[tid]);
        atomicAdd(&g_colsumsq[tid], s_b[tid]);
    }

    if (tid == 0) {
        __threadfence();
        atomicAdd(&g_c3, 1);
        while (atomicAdd(&g_c3, 0) < gridDim.x) { }
    }
    __syncthreads();

    if (tid < DD) {
        float mean = g_colsum[tid] * nInv;
        float var = g_colsumsq[tid] * nInv - mean * mean;
        s_a[tid] = mean;
        s_b[tid] = rsqrtf(var + BN_EPS) * gamma[tid];
    }
    __syncthreads();

    int n4 = N * (DD / 4);
    for (int t = blockIdx.x * 256 + tid; t < n4; t += gridDim.x * 256) {
        int cb = t & 31;
        float4 a  = ((const float4*)g_agg)[t];
        float4 xr = ((const float4*)x)[t];
        float4 m  = ((const float4*)s_a)[cb];
        float4 sc = ((const float4*)s_b)[cb];
        float4 bt = ((const float4*)beta)[cb];
        float4 r;
        r.x = fmaxf((a.x - m.x) * sc.x + bt.x, 0.f) + xr.x;
        r.y = fmaxf((a.y - m.y) * sc.y + bt.y, 0.f) + xr.y;
        r.z = fmaxf((a.z - m.z) * sc.z + bt.z, 0.f) + xr.z;
        r.w = fmaxf((a.w - m.w) * sc.w + bt.w, 0.f) + xr.w;
        ((float4*)out)[t] = r;
    }

    if (tid == 0) {
        if (atomicAdd(&g_c4, 1) == gridDim.x - 1) { g_c3 = 0; g_c4 = 0; }
    }
}

extern "C" void kernel_launch(void* const* d_in, const int* in_sizes, int n_in,
                              void* d_out, int out_size) {
    const float* x     = (const float*)d_in[0];
    const void*  ei    = d_in[1];
    const float* W     = (const float*)d_in[2];
    // d_in[3] = b — cancels exactly through BatchNorm, unused
    const float* gamma = (const float*)d_in[4];
    const float* beta  = (const float*)d_in[5];
    float*       out   = (float*)d_out;

    int N = in_sizes[0] / DD;
    int E = in_sizes[1] / 2;

    static cudaStream_t s2 = nullptr;
    static cudaEvent_t ev_fork = nullptr, ev_join = nullptr;
    if (s2 == nullptr) {
        cudaStreamCreateWithFlags(&s2, cudaStreamNonBlocking);
        cudaEventCreateWithFlags(&ev_fork, cudaEventDisableTiming);
        cudaEventCreateWithFlags(&ev_join, cudaEventDisableTiming);
    }

    // ---- fork: s2 runs the TC GEMM (W cvt inline) ----
    cudaEventRecord(ev_fork, 0);
    cudaStreamWaitEvent(s2, ev_fork, 0);
    int gwarps = (N + 15) / 16;
    k_gemm_tc<<<(gwarps + 7) / 8, 256, 0, s2>>>(x, W, N);
    cudaEventRecord(ev_join, s2);

    // ---- main: fused CSR build (prep+scan+offsets+fill) ----
    k_front<<<B_FRONT, 256>>>(ei, E, N);

    // ---- join, then aggregate ----
    cudaStreamWaitEvent(0, ev_join, 0);
    k_gather<<<(N + 7) / 8, 256>>>(N);

    k_bnfinal<<<BNF_BLOCKS, 256>>>(x, gamma, beta, out, N, 1.0f / (float)N);
}

// round 14
// speedup vs baseline: 1.1482x; 1.1482x over previous
#include <cuda_runtime.h>
#include <cuda_fp16.h>

#define NN 50000
#define EE 800000
#define DD 128
#define BN_EPS 1e-5f
#define SCAN_B 1024
#define NBLK ((NN + SCAN_B - 1) / SCAN_B)   // 49

// ---- scratch (device globals: zero-initialized at module load) ----
__device__ __align__(16) unsigned g_xwh32[NN * 64];  // x@W as half2 pairs
__device__ float    g_agg[NN * DD];
__device__ float    g_dinv[NN];
__device__ int      g_degi[NN];               // re-zeroed by k_gather each run
__device__ int      g_off[NN + 1];
__device__ int      g_cur[NN];
__device__ int      g_adj[EE];
__device__ int      g_bsum[NBLK];
__device__ float    g_colsum[DD];             // zeroed in k_post each run
__device__ float    g_colsumsq[DD];

// ---- per-block edge dtype self-detection (first 256 entries as int64) ----
__device__ __forceinline__ int detect_is64(const void* ei, int N, int tid) {
    __shared__ int s_is64;
    long long v = ((const long long*)ei)[tid & 255];
    int bad = (v < 0 || v >= N) ? 1 : 0;
    int any = __syncthreads_or(bad);
    if (tid == 0) s_is64 = !any;
    __syncthreads();
    return s_is64;
}

// ---- K1: histogram rows (self-detecting) ----
__global__ __launch_bounds__(256) void k_prep(const void* __restrict__ ei, int E, int N) {
    int tid = threadIdx.x;
    int is64 = detect_is64(ei, N, tid);
    int e = blockIdx.x * 256 + tid;
    if (e >= E) return;
    int row = is64 ? (int)((const long long*)ei)[e] : ((const int*)ei)[e];
    if ((unsigned)row < (unsigned)N) atomicAdd(&g_degi[row], 1);
}

// ---- K2: per-block inclusive scan + block totals ----
__global__ __launch_bounds__(SCAN_B) void k_scan1(int N) {
    __shared__ int warp_tot[32];
    int tid = threadIdx.x;
    int lane = tid & 31, wid = tid >> 5;
    int i = blockIdx.x * SCAN_B + tid;
    int v = (i < N) ? g_degi[i] : 0;
    int s = v;
#pragma unroll
    for (int d = 1; d < 32; d <<= 1) {
        int t = __shfl_up_sync(0xffffffffu, s, d);
        if (lane >= d) s += t;
    }
    if (lane == 31) warp_tot[wid] = s;
    __syncthreads();
    if (wid == 0) {
        int t = warp_tot[lane];
        int ws = t;
#pragma unroll
        for (int d = 1; d < 32; d <<= 1) {
            int u = __shfl_up_sync(0xffffffffu, ws, d);
            if (lane >= d) ws += u;
        }
        warp_tot[lane] = ws - t;
    }
    __syncthreads();
    int incl = s + warp_tot[wid];
    if (i < N) g_off[i + 1] = incl;
    if (tid == SCAN_B - 1) g_bsum[blockIdx.x] = incl;
}

// ---- K3: finalize offsets + dinv + fill cursors + zero BN accums ----
__global__ void k_post(int N) {
    int i = blockIdx.x * blockDim.x + threadIdx.x;
    if (i < DD) { g_colsum[i] = 0.0f; g_colsumsq[i] = 0.0f; }
    if (i >= N) return;
    int chunk = i >> 10;
    int boff = 0;
    for (int b = 0; b < chunk; b++) boff += g_bsum[b];
    int incl = g_off[i + 1] + boff;
    g_off[i + 1] = incl;
    int deg = g_degi[i];
    g_cur[i] = incl - deg;
    g_dinv[i] = rsqrtf((float)(deg + 1));
    if (i == 0) g_off[0] = 0;
}

// ---- K4: CSR fill over edge range [e0,e1) (self-detecting) ----
__global__ __launch_bounds__(256) void k_fill(const void* __restrict__ ei,
                                              int e0, int e1, int E, int N) {
    int tid = threadIdx.x;
    int is64 = detect_is64(ei, N, tid);
    int e = e0 + blockIdx.x * 256 + tid;
    if (e >= e1) return;
    int row, col;
    if (is64) {
        row = (int)((const long long*)ei)[e];
        col = (int)((const long long*)ei)[E + e];
    } else {
        row = ((const int*)ei)[e];
        col = ((const int*)ei)[E + e];
    }
    if ((unsigned)row >= (unsigned)N || (unsigned)col >= (unsigned)N) return;
    int pos = atomicAdd(&g_cur[row], 1);
    g_adj[pos] = col;
}

// ---- K5: xw = x @ W via TF32 mma.sync (warp = 16 rows; W cvt inline) ----
__global__ __launch_bounds__(256) void k_gemm_tc(const float* __restrict__ x,
                                                 const float* __restrict__ W, int N) {
    int lane = threadIdx.x & 31;
    int warp = (blockIdx.x * blockDim.x + threadIdx.x) >> 5;
    int r0 = warp * 16;
    if (r0 >= N) return;
    int gid = lane >> 2;
    int tig = lane & 3;

    float c[16][4];
#pragma unroll
    for (int nt = 0; nt < 16; nt++)
        c[nt][0] = c[nt][1] = c[nt][2] = c[nt][3] = 0.f;

    const float* xr0 = x + (r0 + gid) * DD;
    const float* xr1 = xr0 + 8 * DD;

#pragma unroll
    for (int kt = 0; kt < 16; kt++) {
        int k0 = kt * 8;
        unsigned A0, A1, A2, A3;
        {
            float a0 = xr0[k0 + tig];
            float a1 = xr1[k0 + tig];
            float a2 = xr0[k0 + tig + 4];
            float a3 = xr1[k0 + tig + 4];
            asm("cvt.rna.tf32.f32 %0, %1;" : "=r"(A0) : "f"(a0));
            asm("cvt.rna.tf32.f32 %0, %1;" : "=r"(A1) : "f"(a1));
            asm("cvt.rna.tf32.f32 %0, %1;" : "=r"(A2) : "f"(a2));
            asm("cvt.rna.tf32.f32 %0, %1;" : "=r"(A3) : "f"(a3));
        }
#pragma unroll
        for (int nt = 0; nt < 16; nt++) {
            float b0f = W[(k0 + tig) * DD + nt * 8 + gid];
            float b1f = W[(k0 + tig + 4) * DD + nt * 8 + gid];
            unsigned B0, B1;
            asm("cvt.rna.tf32.f32 %0, %1;" : "=r"(B0) : "f"(b0f));
            asm("cvt.rna.tf32.f32 %0, %1;" : "=r"(B1) : "f"(b1f));
            asm volatile(
                "mma.sync.aligned.m16n8k8.row.col.f32.tf32.tf32.f32 "
                "{%0,%1,%2,%3}, {%4,%5,%6,%7}, {%8,%9}, {%0,%1,%2,%3};"
                : "+f"(c[nt][0]), "+f"(c[nt][1]), "+f"(c[nt][2]), "+f"(c[nt][3])
                : "r"(A0), "r"(A1), "r"(A2), "r"(A3), "r"(B0), "r"(B1));
        }
    }

    int row0 = r0 + gid, row1 = r0 + 8 + gid;
#pragma unroll
    for (int nt = 0; nt < 16; nt++) {
        int cH = (nt * 8 + 2 * tig) >> 1;
        __half2 h0 = __float22half2_rn(make_float2(c[nt][0], c[nt][1]));
        __half2 h1 = __float22half2_rn(make_float2(c[nt][2], c[nt][3]));
        g_xwh32[row0 * 64 + cH] = *(unsigned*)&h0;
        g_xwh32[row1 * 64 + cH] = *(unsigned*)&h1;
    }
}

// ---- K6: per-node gather (unroll-4) + re-zero degi for next run ----
__global__ __launch_bounds__(256) void k_gather(int N) {
    int gt = blockIdx.x * blockDim.x + threadIdx.x;
    if (gt < N) g_degi[gt] = 0;
    int lane = threadIdx.x & 31;
    int n = gt >> 5;
    if (n >= N) return;
    int j = g_off[n], end = g_off[n + 1];
    const uint2* xwh = (const uint2*)g_xwh32;

    float4 acc = make_float4(0.f, 0.f, 0.f, 0.f);
    for (; j + 4 <= end; j += 4) {
        int c0 = g_adj[j], c1 = g_adj[j + 1], c2 = g_adj[j + 2], c3 = g_adj[j + 3];
        float w0 = g_dinv[c0], w1 = g_dinv[c1], w2 = g_dinv[c2], w3 = g_dinv[c3];
        uint2 u0 = xwh[c0 * 32 + lane];
        uint2 u1 = xwh[c1 * 32 + lane];
        uint2 u2 = xwh[c2 * 32 + lane];
        uint2 u3 = xwh[c3 * 32 + lane];
        float2 a0 = __half22float2(*(__half2*)&u0.x), b0 = __half22float2(*(__half2*)&u0.y);
        float2 a1 = __half22float2(*(__half2*)&u1.x), b1 = __half22float2(*(__half2*)&u1.y);
        float2 a2 = __half22float2(*(__half2*)&u2.x), b2 = __half22float2(*(__half2*)&u2.y);
        float2 a3 = __half22float2(*(__half2*)&u3.x), b3 = __half22float2(*(__half2*)&u3.y);
        acc.x = fmaf(a0.x, w0, fmaf(a1.x, w1, fmaf(a2.x, w2, fmaf(a3.x, w3, acc.x))));
        acc.y = fmaf(a0.y, w0, fmaf(a1.y, w1, fmaf(a2.y, w2, fmaf(a3.y, w3, acc.y))));
        acc.z = fmaf(b0.x, w0, fmaf(b1.x, w1, fmaf(b2.x, w2, fmaf(b3.x, w3, acc.z))));
        acc.w = fmaf(b0.y, w0, fmaf(b1.y, w1, fmaf(b2.y, w2, fmaf(b3.y, w3, acc.w))));
    }
    for (; j < end; j++) {
        int c0 = g_adj[j];
        float w0 = g_dinv[c0];
        uint2 u0 = xwh[c0 * 32 + lane];
        float2 a0 = __half22float2(*(__half2*)&u0.x), b0 = __half22float2(*(__half2*)&u0.y);
        acc.x = fmaf(a0.x, w0, acc.x);
        acc.y = fmaf(a0.y, w0, acc.y);
        acc.z = fmaf(b0.x, w0, acc.z);
        acc.w = fmaf(b0.y, w0, acc.w);
    }
    float dr = g_dinv[n];
    uint2 us = xwh[n * 32 + lane];
    float2 sa = __half22float2(*(__half2*)&us.x), sb = __half22float2(*(__half2*)&us.y);
    acc.x = (acc.x + sa.x * dr) * dr;
    acc.y = (acc.y + sa.y * dr) * dr;
    acc.z = (acc.z + sb.x * dr) * dr;
    acc.w = (acc.w + sb.y * dr) * dr;
    ((float4*)g_agg)[n * 32 + lane] = acc;
}

// ---- K7: BN column statistics (512 blocks, full occupancy) ----
__global__ void k_bnstats(int N) {
    int c = threadIdx.x;
    float s = 0.f, s2 = 0.f;
    for (int r = blockIdx.x; r < N; r += gridDim.x) {
        float v = g_agg[r * DD + c];
        s += v;
        s2 = fmaf(v, v, s2);
    }
    atomicAdd(&g_colsum[c], s);
    atomicAdd(&g_colsumsq[c], s2);
}

// ---- K8: y = relu((agg-mean)*scale + beta) + x, BN params per-block ----
__global__ __launch_bounds__(256) void k_final(const float* __restrict__ x,
                                               const float* __restrict__ gamma,
                                               const float* __restrict__ beta,
                                               float* __restrict__ out,
                                               int n4, float nInv) {
    __shared__ float s_mean[DD], s_scale[DD];
    int tid = threadIdx.x;
    if (tid < DD) {
        float mean = g_colsum[tid] * nInv;
        float var = g_colsumsq[tid] * nInv - mean * mean;
        s_mean[tid] = mean;
        s_scale[tid] = rsqrtf(var + BN_EPS) * gamma[tid];
    }
    __syncthreads();
    int t = blockIdx.x * blockDim.x + tid;
    if (t >= n4) return;
    int cb = t & 31;
    float4 a  = ((const float4*)g_agg)[t];
    float4 xr = ((const float4*)x)[t];
    float4 m  = ((const float4*)s_mean)[cb];
    float4 s  = ((const float4*)s_scale)[cb];
    float4 bt = ((const float4*)beta)[cb];
    float4 r;
    r.x = fmaxf((a.x - m.x) * s.x + bt.x, 0.f) + xr.x;
    r.y = fmaxf((a.y - m.y) * s.y + bt.y, 0.f) + xr.y;
    r.z = fmaxf((a.z - m.z) * s.z + bt.z, 0.f) + xr.z;
    r.w = fmaxf((a.w - m.w) * s.w + bt.w, 0.f) + xr.w;
    ((float4*)out)[t] = r;
}

extern "C" void kernel_launch(void* const* d_in, const int* in_sizes, int n_in,
                              void* d_out, int out_size) {
    const float* x     = (const float*)d_in[0];
    const void*  ei    = d_in[1];
    const float* W     = (const float*)d_in[2];
    // d_in[3] = b — cancels exactly through BatchNorm, unused
    const float* gamma = (const float*)d_in[4];
    const float* beta  = (const float*)d_in[5];
    float*       out   = (float*)d_out;

    int N = in_sizes[0] / DD;
    int E = in_sizes[1] / 2;
    int nblk = (N + SCAN_B - 1) / SCAN_B;
    int Eh = E / 2;

    static cudaStream_t s2 = nullptr;
    static cudaEvent_t ev_fork = nullptr, ev_post = nullptr, ev_join = nullptr;
    if (s2 == nullptr) {
        cudaStreamCreateWithFlags(&s2, cudaStreamNonBlocking);
        cudaEventCreateWithFlags(&ev_fork, cudaEventDisableTiming);
        cudaEventCreateWithFlags(&ev_post, cudaEventDisableTiming);
        cudaEventCreateWithFlags(&ev_join, cudaEventDisableTiming);
    }

    // ---- fork: s2 runs the TC GEMM (W cvt inline), then helps fill ----
    cudaEventRecord(ev_fork, 0);
    cudaStreamWaitEvent(s2, ev_fork, 0);
    int gwarps = (N + 15) / 16;
    k_gemm_tc<<<(gwarps + 7) / 8, 256, 0, s2>>>(x, W, N);

    // ---- main: CSR build ----
    k_prep<<<(E + 255) / 256, 256>>>(ei, E, N);
    k_scan1<<<nblk, SCAN_B>>>(N);
    k_post<<<(N + 255) / 256, 256>>>(N);
    cudaEventRecord(ev_post, 0);

    // fill split: main does [0,Eh), s2 does [Eh,E) after post
    cudaStreamWaitEvent(s2, ev_post, 0);
    k_fill<<<(E - Eh + 255) / 256, 256, 0, s2>>>(ei, Eh, E, E, N);
    cudaEventRecord(ev_join, s2);
    k_fill<<<(Eh + 255) / 256, 256>>>(ei, 0, Eh, E, N);

    // ---- join, then aggregate ----
    cudaStreamWaitEvent(0, ev_join, 0);
    k_gather<<<(N + 7) / 8, 256>>>(N);

    k_bnstats<<<512, 128>>>(N);

    int n4 = N * (DD / 4);
    k_final<<<(n4 + 255) / 256, 256>>>(x, gamma, beta, out, n4, 1.0f / (float)N);
}

// round 16
// speedup vs baseline: 1.2545x; 1.0925x over previous
#include <cuda_runtime.h>
#include <cuda_fp16.h>

#define NN 50000
#define EE 800000
#define DD 128
#define BN_EPS 1e-5f
#define SCAN_B 1024
#define NBLK ((NN + SCAN_B - 1) / SCAN_B)   // 49
#define BNF_BLOCKS 1184                      // 8 blocks/SM x 148 SMs, co-resident at (256,8)

// ---- scratch (device globals: zero-initialized at module load) ----
__device__ __align__(16) unsigned g_xwh32[NN * 64];  // x@W as half2 pairs
__device__ float    g_agg[NN * DD];
__device__ float    g_dinv[NN];
__device__ int      g_degi[NN];               // re-zeroed by k_gather each run
__device__ int      g_off[NN + 1];
__device__ int      g_cur[NN];
__device__ int      g_adj[EE];
__device__ int      g_bsum[NBLK];
__device__ float    g_colsum[DD];             // zeroed in k_post each run
__device__ float    g_colsumsq[DD];
__device__ int      g_c3, g_c4;               // bnfinal barrier counters

// ---- per-block edge dtype self-detection (first 256 entries as int64) ----
__device__ __forceinline__ int detect_is64(const void* ei, int N, int tid) {
    __shared__ int s_is64;
    long long v = ((const long long*)ei)[tid & 255];
    int bad = (v < 0 || v >= N) ? 1 : 0;
    int any = __syncthreads_or(bad);
    if (tid == 0) s_is64 = !any;
    __syncthreads();
    return s_is64;
}

// ---- K1: histogram rows (self-detecting) ----
__global__ __launch_bounds__(256) void k_prep(const void* __restrict__ ei, int E, int N) {
    int tid = threadIdx.x;
    int is64 = detect_is64(ei, N, tid);
    int e = blockIdx.x * 256 + tid;
    if (e >= E) return;
    int row = is64 ? (int)((const long long*)ei)[e] : ((const int*)ei)[e];
    if ((unsigned)row < (unsigned)N) atomicAdd(&g_degi[row], 1);
}

// ---- K2: per-block inclusive scan + block totals ----
__global__ __launch_bounds__(SCAN_B) void k_scan1(int N) {
    __shared__ int warp_tot[32];
    int tid = threadIdx.x;
    int lane = tid & 31, wid = tid >> 5;
    int i = blockIdx.x * SCAN_B + tid;
    int v = (i < N) ? g_degi[i] : 0;
    int s = v;
#pragma unroll
    for (int d = 1; d < 32; d <<= 1) {
        int t = __shfl_up_sync(0xffffffffu, s, d);
        if (lane >= d) s += t;
    }
    if (lane == 31) warp_tot[wid] = s;
    __syncthreads();
    if (wid == 0) {
        int t = warp_tot[lane];
        int ws = t;
#pragma unroll
        for (int d = 1; d < 32; d <<= 1) {
            int u = __shfl_up_sync(0xffffffffu, ws, d);
            if (lane >= d) ws += u;
        }
        warp_tot[lane] = ws - t;
    }
    __syncthreads();
    int incl = s + warp_tot[wid];
    if (i < N) g_off[i + 1] = incl;
    if (tid == SCAN_B - 1) g_bsum[blockIdx.x] = incl;
}

// ---- K3: finalize offsets + dinv + cursors + zero BN accums ----
// ALL lanes participate in the prefix reduction (no early return before
// shuffles); chunk = i>>10 is warp-uniform since warps are 32-aligned.
__global__ __launch_bounds__(256) void k_post(int N) {
    int tid = threadIdx.x;
    int lane = tid & 31;
    int i = blockIdx.x * 256 + tid;
    int chunk = i >> 10;                 // warp-uniform
    int acc = 0;
    for (int b = lane; b < chunk; b += 32) acc += g_bsum[b];
#pragma unroll
    for (int d = 16; d >= 1; d >>= 1) acc += __shfl_xor_sync(0xffffffffu, acc, d);
    if (i < DD) { g_colsum[i] = 0.0f; g_colsumsq[i] = 0.0f; }
    if (i < N) {
        int incl = g_off[i + 1] + acc;
        g_off[i + 1] = incl;
        int deg = g_degi[i];
        g_cur[i] = incl - deg;
        g_dinv[i] = rsqrtf((float)(deg + 1));
        if (i == 0) g_off[0] = 0;
    }
}

// ---- K4: CSR fill over edge range [e0,e1) (self-detecting) ----
__global__ __launch_bounds__(256) void k_fill(const void* __restrict__ ei,
                                              int e0, int e1, int E, int N) {
    int tid = threadIdx.x;
    int is64 = detect_is64(ei, N, tid);
    int e = e0 + blockIdx.x * 256 + tid;
    if (e >= e1) return;
    int row, col;
    if (is64) {
        row = (int)((const long long*)ei)[e];
        col = (int)((const long long*)ei)[E + e];
    } else {
        row = ((const int*)ei)[e];
        col = ((const int*)ei)[E + e];
    }
    if ((unsigned)row >= (unsigned)N || (unsigned)col >= (unsigned)N) return;
    int pos = atomicAdd(&g_cur[row], 1);
    g_adj[pos] = col;
}

// ---- K5: xw = x @ W via TF32 mma.sync (warp = 16 rows; W cvt inline) ----
__global__ __launch_bounds__(256) void k_gemm_tc(const float* __restrict__ x,
                                                 const float* __restrict__ W, int N) {
    int lane = threadIdx.x & 31;
    int warp = (blockIdx.x * blockDim.x + threadIdx.x) >> 5;
    int r0 = warp * 16;
    if (r0 >= N) return;
    int gid = lane >> 2;
    int tig = lane & 3;

    float c[16][4];
#pragma unroll
    for (int nt = 0; nt < 16; nt++)
        c[nt][0] = c[nt][1] = c[nt][2] = c[nt][3] = 0.f;

    const float* xr0 = x + (r0 + gid) * DD;
    const float* xr1 = xr0 + 8 * DD;

#pragma unroll
    for (int kt = 0; kt < 16; kt++) {
        int k0 = kt * 8;
        unsigned A0, A1, A2, A3;
        {
            float a0 = xr0[k0 + tig];
            float a1 = xr1[k0 + tig];
            float a2 = xr0[k0 + tig + 4];
            float a3 = xr1[k0 + tig + 4];
            asm("cvt.rna.tf32.f32 %0, %1;" : "=r"(A0) : "f"(a0));
            asm("cvt.rna.tf32.f32 %0, %1;" : "=r"(A1) : "f"(a1));
            asm("cvt.rna.tf32.f32 %0, %1;" : "=r"(A2) : "f"(a2));
            asm("cvt.rna.tf32.f32 %0, %1;" : "=r"(A3) : "f"(a3));
        }
#pragma unroll
        for (int nt = 0; nt < 16; nt++) {
            float b0f = W[(k0 + tig) * DD + nt * 8 + gid];
            float b1f = W[(k0 + tig + 4) * DD + nt * 8 + gid];
            unsigned B0, B1;
            asm("cvt.rna.tf32.f32 %0, %1;" : "=r"(B0) : "f"(b0f));
            asm("cvt.rna.tf32.f32 %0, %1;" : "=r"(B1) : "f"(b1f));
            asm volatile(
                "mma.sync.aligned.m16n8k8.row.col.f32.tf32.tf32.f32 "
                "{%0,%1,%2,%3}, {%4,%5,%6,%7}, {%8,%9}, {%0,%1,%2,%3};"
                : "+f"(c[nt][0]), "+f"(c[nt][1]), "+f"(c[nt][2]), "+f"(c[nt][3])
                : "r"(A0), "r"(A1), "r"(A2), "r"(A3), "r"(B0), "r"(B1));
        }
    }

    int row0 = r0 + gid, row1 = r0 + 8 + gid;
#pragma unroll
    for (int nt = 0; nt < 16; nt++) {
        int cH = (nt * 8 + 2 * tig) >> 1;
        __half2 h0 = __float22half2_rn(make_float2(c[nt][0], c[nt][1]));
        __half2 h1 = __float22half2_rn(make_float2(c[nt][2], c[nt][3]));
        g_xwh32[row0 * 64 + cH] = *(unsigned*)&h0;
        g_xwh32[row1 * 64 + cH] = *(unsigned*)&h1;
    }
}

// ---- K6: per-node gather (unroll-4) + re-zero degi for next run ----
__global__ __launch_bounds__(256) void k_gather(int N) {
    int gt = blockIdx.x * blockDim.x + threadIdx.x;
    if (gt < N) g_degi[gt] = 0;
    int lane = threadIdx.x & 31;
    int n = gt >> 5;
    if (n >= N) return;
    int j = g_off[n], end = g_off[n + 1];
    const uint2* xwh = (const uint2*)g_xwh32;

    float4 acc = make_float4(0.f, 0.f, 0.f, 0.f);
    for (; j + 4 <= end; j += 4) {
        int c0 = g_adj[j], c1 = g_adj[j + 1], c2 = g_adj[j + 2], c3 = g_adj[j + 3];
        float w0 = g_dinv[c0], w1 = g_dinv[c1], w2 = g_dinv[c2], w3 = g_dinv[c3];
        uint2 u0 = xwh[c0 * 32 + lane];
        uint2 u1 = xwh[c1 * 32 + lane];
        uint2 u2 = xwh[c2 * 32 + lane];
        uint2 u3 = xwh[c3 * 32 + lane];
        float2 a0 = __half22float2(*(__half2*)&u0.x), b0 = __half22float2(*(__half2*)&u0.y);
        float2 a1 = __half22float2(*(__half2*)&u1.x), b1 = __half22float2(*(__half2*)&u1.y);
        float2 a2 = __half22float2(*(__half2*)&u2.x), b2 = __half22float2(*(__half2*)&u2.y);
        float2 a3 = __half22float2(*(__half2*)&u3.x), b3 = __half22float2(*(__half2*)&u3.y);
        acc.x = fmaf(a0.x, w0, fmaf(a1.x, w1, fmaf(a2.x, w2, fmaf(a3.x, w3, acc.x))));
        acc.y = fmaf(a0.y, w0, fmaf(a1.y, w1, fmaf(a2.y, w2, fmaf(a3.y, w3, acc.y))));
        acc.z = fmaf(b0.x, w0, fmaf(b1.x, w1, fmaf(b2.x, w2, fmaf(b3.x, w3, acc.z))));
        acc.w = fmaf(b0.y, w0, fmaf(b1.y, w1, fmaf(b2.y, w2, fmaf(b3.y, w3, acc.w))));
    }
    for (; j < end; j++) {
        int c0 = g_adj[j];
        float w0 = g_dinv[c0];
        uint2 u0 = xwh[c0 * 32 + lane];
        float2 a0 = __half22float2(*(__half2*)&u0.x), b0 = __half22float2(*(__half2*)&u0.y);
        acc.x = fmaf(a0.x, w0, acc.x);
        acc.y = fmaf(a0.y, w0, acc.y);
        acc.z = fmaf(b0.x, w0, acc.z);
        acc.w = fmaf(b0.y, w0, acc.w);
    }
    float dr = g_dinv[n];
    uint2 us = xwh[n * 32 + lane];
    float2 sa = __half22float2(*(__half2*)&us.x), sb = __half22float2(*(__half2*)&us.y);
    acc.x = (acc.x + sa.x * dr) * dr;
    acc.y = (acc.y + sa.y * dr) * dr;
    acc.z = (acc.z + sb.x * dr) * dr;
    acc.w = (acc.w + sb.y * dr) * dr;
    ((float4*)g_agg)[n * 32 + lane] = acc;
}

// ---- K7: BN stats + finalize fused, FULL-OCCUPANCY persistent grid ----
__global__ __launch_bounds__(256, 8) void k_bnfinal(const float* __restrict__ x,
                                                    const float* __restrict__ gamma,
                                                    const float* __restrict__ beta,
                                                    float* __restrict__ out,
                                                    int N, float nInv) {
    __shared__ float s_a[DD], s_b[DD];
    int tid = threadIdx.x;
    int c = tid & 127, half = tid >> 7;

    // phase A: column partial sums (conflict-free shared merge, 256 REDs/block)
    float s = 0.f, s2 = 0.f;
    for (int r = blockIdx.x * 2 + half; r < N; r += gridDim.x * 2) {
        float v = g_agg[r * DD + c];
        s += v;
        s2 = fmaf(v, v, s2);
    }
    if (half == 0) { s_a[c] = s; s_b[c] = s2; }
    __syncthreads();
    if (half == 1) { s_a[c] += s; s_b[c] += s2; }
    __syncthreads();
    if (tid < DD) {
        atomicAdd(&g_colsum[tid], s_a[tid]);
        atomicAdd(&g_colsumsq[tid], s_b[tid]);
    }

    // grid barrier (1184 co-resident blocks by launch-bounds guarantee)
    if (tid == 0) {
        __threadfence();
        atomicAdd(&g_c3, 1);
        while (atomicAdd(&g_c3, 0) < gridDim.x) { }
    }
    __syncthreads();

    // BN params per block
    if (tid < DD) {
        float mean = g_colsum[tid] * nInv;
        float var = g_colsumsq[tid] * nInv - mean * mean;
        s_a[tid] = mean;
        s_b[tid] = rsqrtf(var + BN_EPS) * gamma[tid];
    }
    __syncthreads();

    // phase B: grid-stride finalize at full occupancy
    int n4 = N * (DD / 4);
    for (int t = blockIdx.x * 256 + tid; t < n4; t += gridDim.x * 256) {
        int cb = t & 31;
        float4 a  = ((const float4*)g_agg)[t];
        float4 xr = ((const float4*)x)[t];
        float4 m  = ((const float4*)s_a)[cb];
        float4 sc = ((const float4*)s_b)[cb];
        float4 bt = ((const float4*)beta)[cb];
        float4 r;
        r.x = fmaxf((a.x - m.x) * sc.x + bt.x, 0.f) + xr.x;
        r.y = fmaxf((a.y - m.y) * sc.y + bt.y, 0.f) + xr.y;
        r.z = fmaxf((a.z - m.z) * sc.z + bt.z, 0.f) + xr.z;
        r.w = fmaxf((a.w - m.w) * sc.w + bt.w, 0.f) + xr.w;
        ((float4*)out)[t] = r;
    }

    // reset counters for next replay
    if (tid == 0) {
        if (atomicAdd(&g_c4, 1) == gridDim.x - 1) { g_c3 = 0; g_c4 = 0; }
    }
}

extern "C" void kernel_launch(void* const* d_in, const int* in_sizes, int n_in,
                              void* d_out, int out_size) {
    const float* x     = (const float*)d_in[0];
    const void*  ei    = d_in[1];
    const float* W     = (const float*)d_in[2];
    // d_in[3] = b — cancels exactly through BatchNorm, unused
    const float* gamma = (const float*)d_in[4];
    const float* beta  = (const float*)d_in[5];
    float*       out   = (float*)d_out;

    int N = in_sizes[0] / DD;
    int E = in_sizes[1] / 2;
    int nblk = (N + SCAN_B - 1) / SCAN_B;
    int Eh = E / 2;

    static cudaStream_t s2 = nullptr;
    static cudaEvent_t ev_fork = nullptr, ev_post = nullptr, ev_join = nullptr;
    if (s2 == nullptr) {
        cudaStreamCreateWithFlags(&s2, cudaStreamNonBlocking);
        cudaEventCreateWithFlags(&ev_fork, cudaEventDisableTiming);
        cudaEventCreateWithFlags(&ev_post, cudaEventDisableTiming);
        cudaEventCreateWithFlags(&ev_join, cudaEventDisableTiming);
    }

    // ---- fork: s2 runs the TC GEMM (W cvt inline), then helps fill ----
    cudaEventRecord(ev_fork, 0);
    cudaStreamWaitEvent(s2, ev_fork, 0);
    int gwarps = (N + 15) / 16;
    k_gemm_tc<<<(gwarps + 7) / 8, 256, 0, s2>>>(x, W, N);

    // ---- main: CSR build ----
    k_prep<<<(E + 255) / 256, 256>>>(ei, E, N);
    k_scan1<<<nblk, SCAN_B>>>(N);
    k_post<<<(N + 255) / 256, 256>>>(N);
    cudaEventRecord(ev_post, 0);

    // fill split: main does [0,Eh), s2 does [Eh,E) after post
    cudaStreamWaitEvent(s2, ev_post, 0);
    k_fill<<<(E - Eh + 255) / 256, 256, 0, s2>>>(ei, Eh, E, E, N);
    cudaEventRecord(ev_join, s2);
    k_fill<<<(Eh + 255) / 256, 256>>>(ei, 0, Eh, E, N);

    // ---- join, then aggregate ----
    cudaStreamWaitEvent(0, ev_join, 0);
    k_gather<<<(N + 7) / 8, 256>>>(N);

    // ---- fused BN stats + finalize (full-occupancy persistent grid) ----
    k_bnfinal<<<BNF_BLOCKS, 256>>>(x, gamma, beta, out, N, 1.0f / (float)N);
}